// round 3
// baseline (speedup 1.0000x reference)
#include <cuda_runtime.h>
#include <cuda_fp16.h>
#include <cstdint>

#define T_TOK  4096
#define DMODEL 1024
#define HID    4096
#define NE     8

#define BM 128
#define BN 64
#define BK 32
#define LDSH 40   // BK + 8 halves padding -> 80B row stride, conflict-free ldmatrix

// ---------------- scratch (static device globals; no allocation allowed) ----
__device__ __half g_xh[T_TOK * DMODEL];            // x in fp16
__device__ __half g_wgh[NE * HID * DMODEL];        // w_g fp16
__device__ __half g_wuh[NE * HID * DMODEL];        // w_u fp16
__device__ __half g_wdh[NE * DMODEL * HID];        // w_d fp16
__device__ __half g_hidden[2 * T_TOK * HID];       // per routed-pair hidden rows
__device__ float  g_contrib[2 * T_TOK * DMODEL];   // per (token,slot) contribution
__device__ int    g_count[NE];
__device__ int    g_base[NE];
__device__ int    g_tok[NE * T_TOK];
__device__ float  g_gatew[NE * T_TOK];
__device__ int    g_slot[NE * T_TOK];
__device__ float  g_fsum[NE];
__device__ float  g_psum[NE];

// ---------------- small PTX helpers ----------------------------------------
__device__ __forceinline__ uint32_t smem_u32(const void* p) {
    return (uint32_t)__cvta_generic_to_shared(p);
}
__device__ __forceinline__ void cp_async16(uint32_t smem, const void* gmem, int src_bytes) {
    asm volatile("cp.async.cg.shared.global [%0], [%1], 16, %2;\n"
                 :: "r"(smem), "l"(gmem), "r"(src_bytes));
}
__device__ __forceinline__ void cp_commit() { asm volatile("cp.async.commit_group;\n"); }
__device__ __forceinline__ void cp_wait_all() { asm volatile("cp.async.wait_all;\n"); }

__device__ __forceinline__ void ldsm4(uint32_t* r, uint32_t a) {
    asm volatile("ldmatrix.sync.aligned.m8n8.x4.shared.b16 {%0,%1,%2,%3}, [%4];"
                 : "=r"(r[0]), "=r"(r[1]), "=r"(r[2]), "=r"(r[3]) : "r"(a));
}
__device__ __forceinline__ void ldsm2(uint32_t* r, uint32_t a) {
    asm volatile("ldmatrix.sync.aligned.m8n8.x2.shared.b16 {%0,%1}, [%2];"
                 : "=r"(r[0]), "=r"(r[1]) : "r"(a));
}
__device__ __forceinline__ void mma_16816(float* c, const uint32_t* a, const uint32_t* b) {
    asm volatile("mma.sync.aligned.m16n8k16.row.col.f32.f16.f16.f32 "
                 "{%0,%1,%2,%3}, {%4,%5,%6,%7}, {%8,%9}, {%0,%1,%2,%3};"
                 : "+f"(c[0]), "+f"(c[1]), "+f"(c[2]), "+f"(c[3])
                 : "r"(a[0]), "r"(a[1]), "r"(a[2]), "r"(a[3]), "r"(b[0]), "r"(b[1]));
}

// ---------------- init ------------------------------------------------------
__global__ void init_kernel() {
    int i = threadIdx.x;
    if (i < NE) { g_count[i] = 0; g_fsum[i] = 0.f; g_psum[i] = 0.f; }
}

// ---------------- fp32 -> fp16 conversion -----------------------------------
__global__ void f2h_kernel(const float* __restrict__ src, int which, int n) {
    __half* dst = (which == 0) ? g_xh : (which == 1) ? g_wgh : (which == 2) ? g_wuh : g_wdh;
    int i = (blockIdx.x * blockDim.x + threadIdx.x) * 4;
    if (i >= n) return;
    float4 v = *reinterpret_cast<const float4*>(src + i);
    *reinterpret_cast<__half2*>(dst + i)     = __floats2half2_rn(v.x, v.y);
    *reinterpret_cast<__half2*>(dst + i + 2) = __floats2half2_rn(v.z, v.w);
}

// ---------------- gating (fp32 exact) ---------------------------------------
__global__ void gate_kernel(const float* __restrict__ x, const float* __restrict__ wgate) {
    int t    = blockIdx.x;
    int warp = threadIdx.x >> 5, lane = threadIdx.x & 31;
    __shared__ float s_logit[NE];
    const float* xr = x + (size_t)t * DMODEL;
    const float* wr = wgate + warp * DMODEL;
    float s = 0.f;
#pragma unroll 8
    for (int i = lane; i < DMODEL; i += 32) s = fmaf(xr[i], wr[i], s);
#pragma unroll
    for (int o = 16; o > 0; o >>= 1) s += __shfl_xor_sync(0xffffffffu, s, o);
    if (lane == 0) s_logit[warp] = s;
    __syncthreads();
    if (threadIdx.x == 0) {
        float l[NE], p[NE];
        float mx = -1e30f;
#pragma unroll
        for (int e = 0; e < NE; e++) { l[e] = s_logit[e]; mx = fmaxf(mx, l[e]); }
        float den = 0.f;
#pragma unroll
        for (int e = 0; e < NE; e++) { p[e] = expf(l[e] - mx); den += p[e]; }
        float inv = 1.f / den;
#pragma unroll
        for (int e = 0; e < NE; e++) atomicAdd(&g_psum[e], p[e] * inv);
        // top-2 (lower index wins ties, matching jax.lax.top_k)
        int i0 = 0;
#pragma unroll
        for (int e = 1; e < NE; e++) if (l[e] > l[i0]) i0 = e;
        int i1 = (i0 == 0) ? 1 : 0;
#pragma unroll
        for (int e = 0; e < NE; e++) if (e != i0 && l[e] > l[i1]) i1 = e;
        float gtop0 = 1.f / (1.f + expf(l[i1] - l[i0]));   // softmax over {l0,l1}
        float gtop1 = 1.f - gtop0;
        atomicAdd(&g_fsum[i0], gtop0);
        atomicAdd(&g_fsum[i1], gtop1);
        int p0 = atomicAdd(&g_count[i0], 1);
        g_tok[i0 * T_TOK + p0] = t; g_gatew[i0 * T_TOK + p0] = gtop0; g_slot[i0 * T_TOK + p0] = 0;
        int p1 = atomicAdd(&g_count[i1], 1);
        g_tok[i1 * T_TOK + p1] = t; g_gatew[i1 * T_TOK + p1] = gtop1; g_slot[i1 * T_TOK + p1] = 1;
    }
}

// ---------------- prefix bases + aux loss -----------------------------------
__global__ void finalize_kernel(float* out, int out_size) {
    if (blockIdx.x == 0 && threadIdx.x == 0) {
        int b = 0;
        float aux = 0.f;
#pragma unroll
        for (int e = 0; e < NE; e++) {
            g_base[e] = b; b += g_count[e];
            aux += (g_fsum[e] * (1.f / T_TOK)) * (g_psum[e] * (1.f / T_TOK));
        }
        aux *= (float)NE;
        for (int i = T_TOK * DMODEL; i < out_size; i++) out[i] = aux;
    }
}

// ---------------- GEMM1: hidden = silu(X Wg^T) * (X Wu^T) -------------------
__global__ void __launch_bounds__(256) ffn1_kernel() {
    const int e   = blockIdx.z;
    const int cnt = g_count[e];
    const int m0  = blockIdx.x * BM;
    if (m0 >= cnt) return;
    const int n0    = blockIdx.y * BN;
    const int valid = min(cnt - m0, BM);
    const int gb    = g_base[e];

    __shared__ __align__(16) __half sA[2][BM * LDSH];
    __shared__ __align__(16) __half sBg[2][BN * LDSH];
    __shared__ __align__(16) __half sBu[2][BN * LDSH];
    __shared__ int s_tok[BM];

    const int tid = threadIdx.x;
    for (int i = tid; i < BM; i += 256)
        s_tok[i] = (i < valid) ? g_tok[e * T_TOK + m0 + i] : 0;
    __syncthreads();

    const __half* wg_b = g_wgh + (size_t)e * HID * DMODEL + (size_t)n0 * DMODEL;
    const __half* wu_b = g_wuh + (size_t)e * HID * DMODEL + (size_t)n0 * DMODEL;

    const int warp = tid >> 5, lane = tid & 31;
    const int wm = (warp >> 1) * 32;
    const int wn = (warp & 1) * 32;

    float cg[2][4][4], cu[2][4][4];
#pragma unroll
    for (int a = 0; a < 2; a++)
#pragma unroll
        for (int b = 0; b < 4; b++)
#pragma unroll
            for (int c = 0; c < 4; c++) { cg[a][b][c] = 0.f; cu[a][b][c] = 0.f; }

    const int a_row = wm + (lane & 15);
    const int a_col = (lane >> 4) << 3;
    const int b_row = wn + (lane & 7);
    const int b_col = ((lane >> 3) & 1) << 3;

    auto load_stage = [&](int bufi, int kt) {
        const int k0 = kt * BK;
#pragma unroll
        for (int i = 0; i < 4; i++) {
            int id = tid + i * 256;
            if (id < 512) {
                int r = id >> 2, ch = id & 3;
                const __half* src = g_xh + (size_t)s_tok[r] * DMODEL + k0 + ch * 8;
                cp_async16(smem_u32(&sA[bufi][r * LDSH + ch * 8]), src, (r < valid) ? 16 : 0);
            } else if (id < 768) {
                int j = id - 512, r = j >> 2, ch = j & 3;
                cp_async16(smem_u32(&sBg[bufi][r * LDSH + ch * 8]),
                           wg_b + (size_t)r * DMODEL + k0 + ch * 8, 16);
            } else {
                int j = id - 768, r = j >> 2, ch = j & 3;
                cp_async16(smem_u32(&sBu[bufi][r * LDSH + ch * 8]),
                           wu_b + (size_t)r * DMODEL + k0 + ch * 8, 16);
            }
        }
    };

    const int KT = DMODEL / BK;
    int buf = 0;
    load_stage(0, 0); cp_commit();
    for (int kt = 0; kt < KT; kt++) {
        cp_wait_all();
        __syncthreads();
        if (kt + 1 < KT) { load_stage(buf ^ 1, kt + 1); cp_commit(); }
#pragma unroll
        for (int ks = 0; ks < 2; ks++) {
            uint32_t aF[2][4];
#pragma unroll
            for (int mf = 0; mf < 2; mf++)
                ldsm4(aF[mf], smem_u32(&sA[buf][(a_row + mf * 16) * LDSH + ks * 16 + a_col]));
#pragma unroll
            for (int nf = 0; nf < 4; nf++) {
                uint32_t bF[2];
                ldsm2(bF, smem_u32(&sBg[buf][(b_row + nf * 8) * LDSH + ks * 16 + b_col]));
                mma_16816(cg[0][nf], aF[0], bF);
                mma_16816(cg[1][nf], aF[1], bF);
            }
#pragma unroll
            for (int nf = 0; nf < 4; nf++) {
                uint32_t bF[2];
                ldsm2(bF, smem_u32(&sBu[buf][(b_row + nf * 8) * LDSH + ks * 16 + b_col]));
                mma_16816(cu[0][nf], aF[0], bF);
                mma_16816(cu[1][nf], aF[1], bF);
            }
        }
        __syncthreads();
        buf ^= 1;
    }

    // epilogue: h = silu(g) * u -> fp16 rows of g_hidden
    const int lr = lane >> 2;
    const int lc = (lane & 3) * 2;
#pragma unroll
    for (int mf = 0; mf < 2; mf++) {
#pragma unroll
        for (int hh = 0; hh < 2; hh++) {
            int rm = wm + mf * 16 + hh * 8 + lr;
            if (rm < valid) {
                __half* orow = g_hidden + (size_t)(gb + m0 + rm) * HID + n0 + wn;
#pragma unroll
                for (int nf = 0; nf < 4; nf++) {
                    float g0 = cg[mf][nf][hh * 2 + 0], g1 = cg[mf][nf][hh * 2 + 1];
                    float u0 = cu[mf][nf][hh * 2 + 0], u1 = cu[mf][nf][hh * 2 + 1];
                    float h0 = g0 / (1.f + expf(-g0)) * u0;
                    float h1 = g1 / (1.f + expf(-g1)) * u1;
                    *reinterpret_cast<__half2*>(orow + nf * 8 + lc) = __floats2half2_rn(h0, h1);
                }
            }
        }
    }
}

// ---------------- GEMM2: y = hidden Wd^T, scaled by gate, scattered ---------
__global__ void __launch_bounds__(256) ffn2_kernel() {
    const int e   = blockIdx.z;
    const int cnt = g_count[e];
    const int m0  = blockIdx.x * BM;
    if (m0 >= cnt) return;
    const int n0    = blockIdx.y * BN;
    const int valid = min(cnt - m0, BM);
    const int gb    = g_base[e];

    __shared__ __align__(16) __half sA[2][BM * LDSH];
    __shared__ __align__(16) __half sB[2][BN * LDSH];
    __shared__ int   s_tk[BM];
    __shared__ float s_gt[BM];
    __shared__ int   s_sl[BM];

    const int tid = threadIdx.x;
    for (int i = tid; i < BM; i += 256) {
        if (i < valid) {
            s_tk[i] = g_tok[e * T_TOK + m0 + i];
            s_gt[i] = g_gatew[e * T_TOK + m0 + i];
            s_sl[i] = g_slot[e * T_TOK + m0 + i];
        } else { s_tk[i] = 0; s_gt[i] = 0.f; s_sl[i] = 0; }
    }
    __syncthreads();

    const __half* wd_b = g_wdh + (size_t)e * DMODEL * HID + (size_t)n0 * HID;
    const __half* a_b  = g_hidden + (size_t)(gb + m0) * HID;

    const int warp = tid >> 5, lane = tid & 31;
    const int wm = (warp >> 1) * 32;
    const int wn = (warp & 1) * 32;

    float cc[2][4][4];
#pragma unroll
    for (int a = 0; a < 2; a++)
#pragma unroll
        for (int b = 0; b < 4; b++)
#pragma unroll
            for (int c = 0; c < 4; c++) cc[a][b][c] = 0.f;

    const int a_row = wm + (lane & 15);
    const int a_col = (lane >> 4) << 3;
    const int b_row = wn + (lane & 7);
    const int b_col = ((lane >> 3) & 1) << 3;

    auto load_stage = [&](int bufi, int kt) {
        const int k0 = kt * BK;
#pragma unroll
        for (int i = 0; i < 3; i++) {
            int id = tid + i * 256;
            if (id < 512) {
                int r = id >> 2, ch = id & 3;
                cp_async16(smem_u32(&sA[bufi][r * LDSH + ch * 8]),
                           a_b + (size_t)r * HID + k0 + ch * 8, (r < valid) ? 16 : 0);
            } else {
                int j = id - 512, r = j >> 2, ch = j & 3;
                cp_async16(smem_u32(&sB[bufi][r * LDSH + ch * 8]),
                           wd_b + (size_t)r * HID + k0 + ch * 8, 16);
            }
        }
    };

    const int KT = HID / BK;
    int buf = 0;
    load_stage(0, 0); cp_commit();
    for (int kt = 0; kt < KT; kt++) {
        cp_wait_all();
        __syncthreads();
        if (kt + 1 < KT) { load_stage(buf ^ 1, kt + 1); cp_commit(); }
#pragma unroll
        for (int ks = 0; ks < 2; ks++) {
            uint32_t aF[2][4];
#pragma unroll
            for (int mf = 0; mf < 2; mf++)
                ldsm4(aF[mf], smem_u32(&sA[buf][(a_row + mf * 16) * LDSH + ks * 16 + a_col]));
#pragma unroll
            for (int nf = 0; nf < 4; nf++) {
                uint32_t bF[2];
                ldsm2(bF, smem_u32(&sB[buf][(b_row + nf * 8) * LDSH + ks * 16 + b_col]));
                mma_16816(cc[0][nf], aF[0], bF);
                mma_16816(cc[1][nf], aF[1], bF);
            }
        }
        __syncthreads();
        buf ^= 1;
    }

    // epilogue: scale by gate, scatter to per-(token,slot) contribution rows
    const int lr = lane >> 2;
    const int lc = (lane & 3) * 2;
#pragma unroll
    for (int mf = 0; mf < 2; mf++) {
#pragma unroll
        for (int hh = 0; hh < 2; hh++) {
            int rm = wm + mf * 16 + hh * 8 + lr;
            if (rm < valid) {
                float gw = s_gt[rm];
                float* orow = g_contrib + ((size_t)s_tk[rm] * 2 + s_sl[rm]) * DMODEL + n0 + wn;
#pragma unroll
                for (int nf = 0; nf < 4; nf++) {
                    float2 v;
                    v.x = cc[mf][nf][hh * 2 + 0] * gw;
                    v.y = cc[mf][nf][hh * 2 + 1] * gw;
                    *reinterpret_cast<float2*>(orow + nf * 8 + lc) = v;
                }
            }
        }
    }
}

// ---------------- combine the two slots -------------------------------------
__global__ void combine_kernel(float* __restrict__ out) {
    int i = (blockIdx.x * blockDim.x + threadIdx.x) * 4;
    int t = i >> 10;          // / DMODEL
    int d = i & (DMODEL - 1);
    float4 a = *reinterpret_cast<const float4*>(&g_contrib[(size_t)t * 2 * DMODEL + d]);
    float4 b = *reinterpret_cast<const float4*>(&g_contrib[(size_t)t * 2 * DMODEL + DMODEL + d]);
    float4 r;
    r.x = a.x + b.x; r.y = a.y + b.y; r.z = a.z + b.z; r.w = a.w + b.w;
    *reinterpret_cast<float4*>(out + i) = r;
}

// ---------------- launch -----------------------------------------------------
extern "C" void kernel_launch(void* const* d_in, const int* in_sizes, int n_in,
                              void* d_out, int out_size) {
    const float* x     = (const float*)d_in[0];
    const float* wgate = (const float*)d_in[1];
    // d_in[2] = w_noise (unused in eval mode)
    const float* wg = (const float*)d_in[3];
    const float* wu = (const float*)d_in[4];
    const float* wd = (const float*)d_in[5];
    float* out = (float*)d_out;

    init_kernel<<<1, 32>>>();

    const int NX = T_TOK * DMODEL;
    const int NW = NE * HID * DMODEL;
    f2h_kernel<<<NX / 4 / 256, 256>>>(x, 0, NX);
    f2h_kernel<<<NW / 4 / 256, 256>>>(wg, 1, NW);
    f2h_kernel<<<NW / 4 / 256, 256>>>(wu, 2, NW);
    f2h_kernel<<<NW / 4 / 256, 256>>>(wd, 3, NW);

    gate_kernel<<<T_TOK, 256>>>(x, wgate);
    finalize_kernel<<<1, 32>>>(out, out_size);

    ffn1_kernel<<<dim3(T_TOK / BM, HID / BN, NE), 256>>>();
    ffn2_kernel<<<dim3(T_TOK / BM, DMODEL / BN, NE), 256>>>();

    combine_kernel<<<(T_TOK * DMODEL / 4) / 256, 256>>>(out);
}

// round 5
// speedup vs baseline: 1.1941x; 1.1941x over previous
#include <cuda_runtime.h>
#include <cuda_fp16.h>
#include <cstdint>

#define T_TOK  4096
#define DMODEL 1024
#define HID    4096
#define NE     8

#define BM 128
#define BK 64          // K chunk (halves) per stage
#define LD1 72         // row stride in halves (64 + 8 pad) -> conflict-free ldmatrix

// ---------------- scratch (static device globals) ---------------------------
__device__ __half g_xh[T_TOK * DMODEL];
__device__ __half g_wgh[NE * HID * DMODEL];
__device__ __half g_wuh[NE * HID * DMODEL];
__device__ __half g_wdh[NE * DMODEL * HID];
__device__ __half g_hidden[2 * T_TOK * HID];
__device__ float  g_contrib[2 * T_TOK * DMODEL];
__device__ int    g_count[NE];
__device__ int    g_base[NE];
__device__ int    g_tok[NE * T_TOK];
__device__ float  g_gatew[NE * T_TOK];
__device__ int    g_slot[NE * T_TOK];
__device__ float  g_fsum[NE];
__device__ float  g_psum[NE];

// ---------------- PTX helpers ------------------------------------------------
__device__ __forceinline__ uint32_t smem_u32(const void* p) {
    return (uint32_t)__cvta_generic_to_shared(p);
}
__device__ __forceinline__ void cp_async16(uint32_t smem, const void* gmem, int src_bytes) {
    asm volatile("cp.async.cg.shared.global [%0], [%1], 16, %2;\n"
                 :: "r"(smem), "l"(gmem), "r"(src_bytes));
}
__device__ __forceinline__ void cp_commit() { asm volatile("cp.async.commit_group;\n"); }
__device__ __forceinline__ void cp_wait2()  { asm volatile("cp.async.wait_group 2;\n"); }

__device__ __forceinline__ void ldsm4(uint32_t* r, uint32_t a) {
    asm volatile("ldmatrix.sync.aligned.m8n8.x4.shared.b16 {%0,%1,%2,%3}, [%4];"
                 : "=r"(r[0]), "=r"(r[1]), "=r"(r[2]), "=r"(r[3]) : "r"(a));
}
__device__ __forceinline__ void mma_16816(float* c, const uint32_t* a, uint32_t b0, uint32_t b1) {
    asm volatile("mma.sync.aligned.m16n8k16.row.col.f32.f16.f16.f32 "
                 "{%0,%1,%2,%3}, {%4,%5,%6,%7}, {%8,%9}, {%0,%1,%2,%3};"
                 : "+f"(c[0]), "+f"(c[1]), "+f"(c[2]), "+f"(c[3])
                 : "r"(a[0]), "r"(a[1]), "r"(a[2]), "r"(a[3]), "r"(b0), "r"(b1));
}

// ---------------- init -------------------------------------------------------
__global__ void init_kernel() {
    int i = threadIdx.x;
    if (i < NE) { g_count[i] = 0; g_fsum[i] = 0.f; g_psum[i] = 0.f; }
}

// ---------------- fp32 -> fp16 conversion ------------------------------------
__global__ void f2h_x_kernel(const float* __restrict__ src) {
    size_t i = ((size_t)blockIdx.x * blockDim.x + threadIdx.x) * 8;
    float4 v0 = *reinterpret_cast<const float4*>(src + i);
    float4 v1 = *reinterpret_cast<const float4*>(src + i + 4);
    __half2 h[4] = {__floats2half2_rn(v0.x, v0.y), __floats2half2_rn(v0.z, v0.w),
                    __floats2half2_rn(v1.x, v1.y), __floats2half2_rn(v1.z, v1.w)};
    *reinterpret_cast<uint4*>(g_xh + i) = *reinterpret_cast<uint4*>(h);
}
__global__ void f2h_w_kernel(const float* __restrict__ a, const float* __restrict__ b,
                             const float* __restrict__ c) {
    int which = blockIdx.y;
    const float* src = (which == 0) ? a : (which == 1) ? b : c;
    __half* dst = (which == 0) ? g_wgh : (which == 1) ? g_wuh : g_wdh;
    size_t i = ((size_t)blockIdx.x * blockDim.x + threadIdx.x) * 8;
    float4 v0 = *reinterpret_cast<const float4*>(src + i);
    float4 v1 = *reinterpret_cast<const float4*>(src + i + 4);
    __half2 h[4] = {__floats2half2_rn(v0.x, v0.y), __floats2half2_rn(v0.z, v0.w),
                    __floats2half2_rn(v1.x, v1.y), __floats2half2_rn(v1.z, v1.w)};
    *reinterpret_cast<uint4*>(dst + i) = *reinterpret_cast<uint4*>(h);
}

// ---------------- gating (fp32 exact) ----------------------------------------
__global__ void gate_kernel(const float* __restrict__ x, const float* __restrict__ wgate) {
    int t    = blockIdx.x;
    int warp = threadIdx.x >> 5, lane = threadIdx.x & 31;
    __shared__ float s_logit[NE];
    const float* xr = x + (size_t)t * DMODEL;
    const float* wr = wgate + warp * DMODEL;
    float s = 0.f;
#pragma unroll 8
    for (int i = lane; i < DMODEL; i += 32) s = fmaf(xr[i], wr[i], s);
#pragma unroll
    for (int o = 16; o > 0; o >>= 1) s += __shfl_xor_sync(0xffffffffu, s, o);
    if (lane == 0) s_logit[warp] = s;
    __syncthreads();
    if (threadIdx.x == 0) {
        float l[NE], p[NE];
        float mx = -1e30f;
#pragma unroll
        for (int e = 0; e < NE; e++) { l[e] = s_logit[e]; mx = fmaxf(mx, l[e]); }
        float den = 0.f;
#pragma unroll
        for (int e = 0; e < NE; e++) { p[e] = expf(l[e] - mx); den += p[e]; }
        float inv = 1.f / den;
#pragma unroll
        for (int e = 0; e < NE; e++) atomicAdd(&g_psum[e], p[e] * inv);
        int i0 = 0;
#pragma unroll
        for (int e = 1; e < NE; e++) if (l[e] > l[i0]) i0 = e;
        int i1 = (i0 == 0) ? 1 : 0;
#pragma unroll
        for (int e = 0; e < NE; e++) if (e != i0 && l[e] > l[i1]) i1 = e;
        float gtop0 = 1.f / (1.f + expf(l[i1] - l[i0]));
        float gtop1 = 1.f - gtop0;
        atomicAdd(&g_fsum[i0], gtop0);
        atomicAdd(&g_fsum[i1], gtop1);
        int p0 = atomicAdd(&g_count[i0], 1);
        g_tok[i0 * T_TOK + p0] = t; g_gatew[i0 * T_TOK + p0] = gtop0; g_slot[i0 * T_TOK + p0] = 0;
        int p1 = atomicAdd(&g_count[i1], 1);
        g_tok[i1 * T_TOK + p1] = t; g_gatew[i1 * T_TOK + p1] = gtop1; g_slot[i1 * T_TOK + p1] = 1;
    }
}

// ---------------- prefix bases + aux loss ------------------------------------
__global__ void finalize_kernel(float* out, int out_size) {
    if (blockIdx.x == 0 && threadIdx.x == 0) {
        int b = 0;
        float aux = 0.f;
#pragma unroll
        for (int e = 0; e < NE; e++) {
            g_base[e] = b; b += g_count[e];
            aux += (g_fsum[e] * (1.f / T_TOK)) * (g_psum[e] * (1.f / T_TOK));
        }
        aux *= (float)NE;
        for (int i = T_TOK * DMODEL; i < out_size; i++) out[i] = aux;
    }
}

// ============ FFN1: hidden = silu(X Wg^T) * (X Wu^T),  BN=64 =================
// stage: A 128*72*2 = 18432 | Bg 64*72*2 = 9216 | Bu 9216  => 36864 B; 3 stages
#define F1_STG   36864
#define F1_BGOFF 18432
#define F1_BUOFF 27648
#define FFN1_SMEM (3 * F1_STG + 256)

__global__ void __launch_bounds__(256, 1) ffn1_kernel() {
    const int e   = blockIdx.z;
    const int cnt = g_count[e];
    const int m0  = blockIdx.x * BM;
    if (m0 >= cnt) return;
    const int n0    = blockIdx.y * 64;
    const int valid = min(cnt - m0, BM);
    const int gb    = g_base[e];

    extern __shared__ char dsm[];
    uint32_t base = (smem_u32(dsm) + 255u) & ~255u;

    __shared__ int s_tok[BM];
    const int tid = threadIdx.x, warp = tid >> 5, lane = tid & 31;
    for (int i = tid; i < BM; i += 256)
        s_tok[i] = (i < valid) ? g_tok[e * T_TOK + m0 + i] : 0;
    __syncthreads();

    const __half* wg_b = g_wgh + (size_t)e * HID * DMODEL + (size_t)n0 * DMODEL;
    const __half* wu_b = g_wuh + (size_t)e * HID * DMODEL + (size_t)n0 * DMODEL;

    const int wm = (warp >> 1) * 32;
    const int wn = (warp & 1) * 32;

    float cg[2][4][4], cu[2][4][4];
#pragma unroll
    for (int a = 0; a < 2; a++)
#pragma unroll
        for (int b = 0; b < 4; b++)
#pragma unroll
            for (int c = 0; c < 4; c++) { cg[a][b][c] = 0.f; cu[a][b][c] = 0.f; }

    auto load_chunk = [&](int kt, int st) {
        const int k0 = kt * BK;
        const uint32_t sb = base + st * F1_STG;
#pragma unroll
        for (int i = 0; i < 8; i++) {
            int id = tid + i * 256;
            if (id < 1024) {
                int r = id >> 3, ch = id & 7;
                const __half* src = g_xh + (size_t)s_tok[r] * DMODEL + k0 + ch * 8;
                cp_async16(sb + r * (LD1 * 2) + ch * 16, src, (r < valid) ? 16 : 0);
            } else if (id < 1536) {
                int j = id - 1024, r = j >> 3, ch = j & 7;
                cp_async16(sb + F1_BGOFF + r * (LD1 * 2) + ch * 16,
                           wg_b + (size_t)r * DMODEL + k0 + ch * 8, 16);
            } else {
                int j = id - 1536, r = j >> 3, ch = j & 7;
                cp_async16(sb + F1_BUOFF + r * (LD1 * 2) + ch * 16,
                           wu_b + (size_t)r * DMODEL + k0 + ch * 8, 16);
            }
        }
    };

    const int lrow = lane & 15;
    const int lcol = (lane >> 4) << 3;

    const int KT = DMODEL / BK;   // 16
    load_chunk(0, 0); cp_commit();
    load_chunk(1, 1); cp_commit();
    load_chunk(2, 2); cp_commit();

    uint32_t aF[2][2][4], bG[2][2][4], bU[2][2][4];

    for (int kt = 0; kt < KT; kt++) {
        const int st = kt % 3;
        const uint32_t sb = base + st * F1_STG;
        cp_wait2();
        __syncthreads();

        auto load_frags = [&](int buf, int ks) {
            const uint32_t co = (ks * 16 + lcol) * 2;
#pragma unroll
            for (int mf = 0; mf < 2; mf++)
                ldsm4(aF[buf][mf], sb + (wm + mf * 16 + lrow) * (LD1 * 2) + co);
#pragma unroll
            for (int p = 0; p < 2; p++)
                ldsm4(bG[buf][p], sb + F1_BGOFF + (wn + p * 16 + lrow) * (LD1 * 2) + co);
#pragma unroll
            for (int p = 0; p < 2; p++)
                ldsm4(bU[buf][p], sb + F1_BUOFF + (wn + p * 16 + lrow) * (LD1 * 2) + co);
        };

        load_frags(0, 0);
        int buf = 0;
#pragma unroll
        for (int ks = 0; ks < 4; ks++) {
            if (ks < 3) load_frags(buf ^ 1, ks + 1);
#pragma unroll
            for (int nf = 0; nf < 4; nf++) {
                const int p = nf >> 1, o = nf & 1;
                mma_16816(cg[0][nf], aF[buf][0], bG[buf][p][o], bG[buf][p][o + 2]);
                mma_16816(cg[1][nf], aF[buf][1], bG[buf][p][o], bG[buf][p][o + 2]);
            }
#pragma unroll
            for (int nf = 0; nf < 4; nf++) {
                const int p = nf >> 1, o = nf & 1;
                mma_16816(cu[0][nf], aF[buf][0], bU[buf][p][o], bU[buf][p][o + 2]);
                mma_16816(cu[1][nf], aF[buf][1], bU[buf][p][o], bU[buf][p][o + 2]);
            }
            buf ^= 1;
        }
        __syncthreads();
        if (kt + 3 < KT) load_chunk(kt + 3, st);
        cp_commit();    // always: keep group accounting uniform
    }

    // epilogue: h = silu(g) * u -> fp16 rows of g_hidden
    const int lr = lane >> 2;
    const int lc = (lane & 3) * 2;
#pragma unroll
    for (int mf = 0; mf < 2; mf++) {
#pragma unroll
        for (int hh = 0; hh < 2; hh++) {
            int rm = wm + mf * 16 + hh * 8 + lr;
            if (rm < valid) {
                __half* orow = g_hidden + (size_t)(gb + m0 + rm) * HID + n0 + wn;
#pragma unroll
                for (int nf = 0; nf < 4; nf++) {
                    float g0 = cg[mf][nf][hh * 2 + 0], g1 = cg[mf][nf][hh * 2 + 1];
                    float u0 = cu[mf][nf][hh * 2 + 0], u1 = cu[mf][nf][hh * 2 + 1];
                    float h0 = g0 / (1.f + expf(-g0)) * u0;
                    float h1 = g1 / (1.f + expf(-g1)) * u1;
                    *reinterpret_cast<__half2*>(orow + nf * 8 + lc) = __floats2half2_rn(h0, h1);
                }
            }
        }
    }
}

// ============ FFN2: y = hidden Wd^T (gate-scaled, scattered),  BN=128 ========
// stage: A 128*72*2 = 18432 | B 128*72*2 = 18432  => 36864 B; 3 stages
#define F2_STG  36864
#define F2_BOFF 18432
#define FFN2_SMEM (3 * F2_STG + 256)

__global__ void __launch_bounds__(256, 1) ffn2_kernel() {
    const int e   = blockIdx.z;
    const int cnt = g_count[e];
    const int m0  = blockIdx.x * BM;
    if (m0 >= cnt) return;
    const int n0    = blockIdx.y * 128;
    const int valid = min(cnt - m0, BM);
    const int gb    = g_base[e];

    extern __shared__ char dsm[];
    uint32_t base = (smem_u32(dsm) + 255u) & ~255u;

    __shared__ int   s_tk[BM];
    __shared__ float s_gt[BM];
    __shared__ int   s_sl[BM];

    const int tid = threadIdx.x, warp = tid >> 5, lane = tid & 31;
    for (int i = tid; i < BM; i += 256) {
        if (i < valid) {
            s_tk[i] = g_tok[e * T_TOK + m0 + i];
            s_gt[i] = g_gatew[e * T_TOK + m0 + i];
            s_sl[i] = g_slot[e * T_TOK + m0 + i];
        } else { s_tk[i] = 0; s_gt[i] = 0.f; s_sl[i] = 0; }
    }
    __syncthreads();

    const __half* wd_b = g_wdh + (size_t)e * DMODEL * HID + (size_t)n0 * HID;
    const __half* a_b  = g_hidden + (size_t)(gb + m0) * HID;

    const int wm = (warp >> 1) * 32;   // 4 warp-rows
    const int wn = (warp & 1) * 64;    // 2 warp-cols, 64 wide each

    float cc[2][8][4];
#pragma unroll
    for (int a = 0; a < 2; a++)
#pragma unroll
        for (int b = 0; b < 8; b++)
#pragma unroll
            for (int c = 0; c < 4; c++) cc[a][b][c] = 0.f;

    auto load_chunk = [&](int kt, int st) {
        const int k0 = kt * BK;
        const uint32_t sb = base + st * F2_STG;
#pragma unroll
        for (int i = 0; i < 8; i++) {
            int id = tid + i * 256;
            if (id < 1024) {
                int r = id >> 3, ch = id & 7;
                cp_async16(sb + r * (LD1 * 2) + ch * 16,
                           a_b + (size_t)r * HID + k0 + ch * 8, (r < valid) ? 16 : 0);
            } else {
                int j = id - 1024, r = j >> 3, ch = j & 7;
                cp_async16(sb + F2_BOFF + r * (LD1 * 2) + ch * 16,
                           wd_b + (size_t)r * HID + k0 + ch * 8, 16);
            }
        }
    };

    const int lrow = lane & 15;
    const int lcol = (lane >> 4) << 3;

    const int KT = HID / BK;   // 64
    load_chunk(0, 0); cp_commit();
    load_chunk(1, 1); cp_commit();
    load_chunk(2, 2); cp_commit();

    uint32_t aF[2][2][4], bF[2][4][4];

    for (int kt = 0; kt < KT; kt++) {
        const int st = kt % 3;
        const uint32_t sb = base + st * F2_STG;
        cp_wait2();
        __syncthreads();

        auto load_frags = [&](int buf, int ks) {
            const uint32_t co = (ks * 16 + lcol) * 2;
#pragma unroll
            for (int mf = 0; mf < 2; mf++)
                ldsm4(aF[buf][mf], sb + (wm + mf * 16 + lrow) * (LD1 * 2) + co);
#pragma unroll
            for (int p = 0; p < 4; p++)
                ldsm4(bF[buf][p], sb + F2_BOFF + (wn + p * 16 + lrow) * (LD1 * 2) + co);
        };

        load_frags(0, 0);
        int buf = 0;
#pragma unroll
        for (int ks = 0; ks < 4; ks++) {
            if (ks < 3) load_frags(buf ^ 1, ks + 1);
#pragma unroll
            for (int nf = 0; nf < 8; nf++) {
                const int p = nf >> 1, o = nf & 1;
                mma_16816(cc[0][nf], aF[buf][0], bF[buf][p][o], bF[buf][p][o + 2]);
                mma_16816(cc[1][nf], aF[buf][1], bF[buf][p][o], bF[buf][p][o + 2]);
            }
            buf ^= 1;
        }
        __syncthreads();
        if (kt + 3 < KT) load_chunk(kt + 3, st);
        cp_commit();
    }

    // epilogue: scale by gate, scatter to per-(token,slot) contribution rows
    const int lr = lane >> 2;
    const int lc = (lane & 3) * 2;
#pragma unroll
    for (int mf = 0; mf < 2; mf++) {
#pragma unroll
        for (int hh = 0; hh < 2; hh++) {
            int rm = wm + mf * 16 + hh * 8 + lr;
            if (rm < valid) {
                float gw = s_gt[rm];
                float* orow = g_contrib + ((size_t)s_tk[rm] * 2 + s_sl[rm]) * DMODEL + n0 + wn;
#pragma unroll
                for (int nf = 0; nf < 8; nf++) {
                    float2 v;
                    v.x = cc[mf][nf][hh * 2 + 0] * gw;
                    v.y = cc[mf][nf][hh * 2 + 1] * gw;
                    *reinterpret_cast<float2*>(orow + nf * 8 + lc) = v;
                }
            }
        }
    }
}

// ---------------- combine the two slots --------------------------------------
__global__ void combine_kernel(float* __restrict__ out) {
    int i = (blockIdx.x * blockDim.x + threadIdx.x) * 4;
    int t = i >> 10;
    int d = i & (DMODEL - 1);
    float4 a = *reinterpret_cast<const float4*>(&g_contrib[(size_t)t * 2 * DMODEL + d]);
    float4 b = *reinterpret_cast<const float4*>(&g_contrib[(size_t)t * 2 * DMODEL + DMODEL + d]);
    float4 r;
    r.x = a.x + b.x; r.y = a.y + b.y; r.z = a.z + b.z; r.w = a.w + b.w;
    *reinterpret_cast<float4*>(out + i) = r;
}

// ---------------- launch ------------------------------------------------------
extern "C" void kernel_launch(void* const* d_in, const int* in_sizes, int n_in,
                              void* d_out, int out_size) {
    const float* x     = (const float*)d_in[0];
    const float* wgate = (const float*)d_in[1];
    const float* wg = (const float*)d_in[3];
    const float* wu = (const float*)d_in[4];
    const float* wd = (const float*)d_in[5];
    float* out = (float*)d_out;

    cudaFuncSetAttribute(ffn1_kernel, cudaFuncAttributeMaxDynamicSharedMemorySize, FFN1_SMEM);
    cudaFuncSetAttribute(ffn2_kernel, cudaFuncAttributeMaxDynamicSharedMemorySize, FFN2_SMEM);

    init_kernel<<<1, 32>>>();

    const int NX = T_TOK * DMODEL;
    const int NW = NE * HID * DMODEL;
    f2h_x_kernel<<<NX / 8 / 256, 256>>>(x);
    f2h_w_kernel<<<dim3(NW / 8 / 256, 3, 1), 256>>>(wg, wu, wd);

    gate_kernel<<<T_TOK, 256>>>(x, wgate);
    finalize_kernel<<<1, 32>>>(out, out_size);

    ffn1_kernel<<<dim3(T_TOK / BM, HID / 64, NE), 256, FFN1_SMEM>>>();
    ffn2_kernel<<<dim3(T_TOK / BM, DMODEL / 128, NE), 256, FFN2_SMEM>>>();

    combine_kernel<<<(T_TOK * DMODEL / 4) / 256, 256>>>(out);
}